// round 2
// baseline (speedup 1.0000x reference)
#include <cuda_runtime.h>
#include <cuda_bf16.h>

// Lyapunov spectrum via Jacobian + row Gram-Schmidt.
// traj: (T=2048, V=3, B=8192) float32, laid out t*(3*8192) + v*8192 + b.
// out:  (3, 8192) float32.
//
// One thread per batch element. Sequential scan over T (not parallelizable:
// row-GS of J@Q gives L*Q' with L on the LEFT, so products don't telescope).
// 4-deep prefetch ring hides DRAM latency behind the ~150-cycle GS chain.

#define T_STEPS 2048
#define BATCH   8192
#define STRIDE_T (3 * BATCH)   // 24576

__device__ __forceinline__ float frsqrt_approx(float x) {
    float r;
    asm("rsqrt.approx.f32 %0, %1;" : "=f"(r) : "f"(x));
    return r;
}
__device__ __forceinline__ float flog2_approx(float x) {
    float r;
    asm("lg2.approx.f32 %0, %1;" : "=f"(r) : "f"(x));
    return r;
}

__global__ void __launch_bounds__(32, 16)
lya_spec_kernel(const float* __restrict__ traj, float* __restrict__ out)
{
    const int b = blockIdx.x * blockDim.x + threadIdx.x;
    if (b >= BATCH) return;

    // Jacobian constants: J = I + DT * [[-s, s, 0], [r - z, -1, -x], [y, x, -beta]]
    const float J00 = 0.9f;          // 1 - DT*SIGMA
    const float J01 = 0.1f;          // DT*SIGMA
    const float J11 = 0.99f;         // 1 - DT
    const float J22 = 0.97333336f;   // 1 - DT*8/3

    // Q rows (row-major), init identity
    float q00 = 1.f, q01 = 0.f, q02 = 0.f;
    float q10 = 0.f, q11 = 1.f, q12 = 0.f;
    float q20 = 0.f, q21 = 0.f, q22 = 1.f;

    // log2-norm accumulators
    float a0 = 0.f, a1 = 0.f, a2 = 0.f;

    const float* pt = traj + b;

    // 4-deep prefetch ring
    float bx[4], by[4], bz[4];
#pragma unroll
    for (int i = 0; i < 4; ++i) {
        const float* p = pt + i * STRIDE_T;
        bx[i] = p[0];
        by[i] = p[BATCH];
        bz[i] = p[2 * BATCH];
    }

#pragma unroll 4
    for (int t = 0; t < T_STEPS; ++t) {
        const int s = t & 3;
        const float x = bx[s];
        const float y = by[s];
        const float z = bz[s];

        // prefetch t+4
        if (t + 4 < T_STEPS) {
            const float* p = pt + (t + 4) * STRIDE_T;
            bx[s] = p[0];
            by[s] = p[BATCH];
            bz[s] = p[2 * BATCH];
        }

        // data-dependent Jacobian entries
        const float j10 = 0.01f * (28.0f - z);
        const float j12 = -0.01f * x;
        const float j21 = 0.01f * x;
        const float j20 = 0.01f * y;

        // M = J @ Q  (rows)
        const float m00 = J00 * q00 + J01 * q10;
        const float m01 = J00 * q01 + J01 * q11;
        const float m02 = J00 * q02 + J01 * q12;

        const float m10 = j10 * q00 + J11 * q10 + j12 * q20;
        const float m11 = j10 * q01 + J11 * q11 + j12 * q21;
        const float m12 = j10 * q02 + J11 * q12 + j12 * q22;

        const float m20 = j20 * q00 + j21 * q10 + J22 * q20;
        const float m21 = j20 * q01 + j21 * q11 + J22 * q21;
        const float m22 = j20 * q02 + j21 * q12 + J22 * q22;

        // ---- Gram-Schmidt on rows ----
        // k = 0
        const float s0 = m00 * m00 + m01 * m01 + m02 * m02;
        const float inv0 = frsqrt_approx(s0);
        q00 = m00 * inv0; q01 = m01 * inv0; q02 = m02 * inv0;
        a0 += flog2_approx(s0);

        // k = 1
        const float d10 = q00 * m10 + q01 * m11 + q02 * m12;
        float r10 = m10 - d10 * q00;
        float r11 = m11 - d10 * q01;
        float r12 = m12 - d10 * q02;
        const float s1 = r10 * r10 + r11 * r11 + r12 * r12;
        const float inv1 = frsqrt_approx(s1);
        q10 = r10 * inv1; q11 = r11 * inv1; q12 = r12 * inv1;
        a1 += flog2_approx(s1);

        // k = 2 (sequential projections, faithful to reference)
        const float d20 = q00 * m20 + q01 * m21 + q02 * m22;
        float r20 = m20 - d20 * q00;
        float r21 = m21 - d20 * q01;
        float r22 = m22 - d20 * q02;
        const float d21 = q10 * r20 + q11 * r21 + q12 * r22;
        r20 -= d21 * q10;
        r21 -= d21 * q11;
        r22 -= d21 * q12;
        const float s2 = r20 * r20 + r21 * r21 + r22 * r22;
        const float inv2 = frsqrt_approx(s2);
        q20 = r20 * inv2; q21 = r21 * inv2; q22 = r22 * inv2;
        a2 += flog2_approx(s2);
    }

    // lambda_k = sum_t ln(n_k) / (T*DT) = 0.5*ln(2)/(T*DT) * sum_t log2(s_k)
    const float C = 0.0169225385f;   // 0.5 * ln(2) / 20.48
    out[b]             = a0 * C;
    out[BATCH + b]     = a1 * C;
    out[2 * BATCH + b] = a2 * C;
}

extern "C" void kernel_launch(void* const* d_in, const int* in_sizes, int n_in,
                              void* d_out, int out_size)
{
    const float* traj = (const float*)d_in[0];
    float* out = (float*)d_out;
    lya_spec_kernel<<<BATCH / 32, 32>>>(traj, out);
}

// round 3
// speedup vs baseline: 4.5758x; 4.5758x over previous
#include <cuda_runtime.h>
#include <cuda_bf16.h>

// Lyapunov spectrum, reformulated.
//
// Key identity: row-Gram-Schmidt commutes with right-multiplication by an
// orthogonal matrix (all inner products invariant). Q0 = I and GS keeps Q
// orthonormal, so the per-step GS norms of J(state)@Q equal those of
// GS_rows(J(state)) alone. The "scan" carries no information into the output:
//   lambda_k(b) = sum_t log(n_k(x_t,y_t,z_t)) / (T*DT)
// with n_k the row-GS norms of the 3x3 matrix
//   J = [[0.9, 0.1, 0], [0.28-0.01z, 0.99, -0.01x], [0.01y, 0.01x, 0.97333334]]
// Row 0 norm is constant sqrt(0.82) -> lambda_0 = 50*ln(0.82) for all b.
// Pure map-reduce over (t, b): embarrassingly parallel.

#define T_STEPS 2048
#define BATCH   8192
#define STRIDE_T (3 * BATCH)   // 24576 floats per time step

__device__ __forceinline__ float frsqrt_approx(float x) {
    float r; asm("rsqrt.approx.f32 %0, %1;" : "=f"(r) : "f"(x)); return r;
}
__device__ __forceinline__ float flog2_approx(float x) {
    float r; asm("lg2.approx.f32 %0, %1;" : "=f"(r) : "f"(x)); return r;
}

// block: 256 threads = 32 b-lanes x 8 t-lanes. grid: 256 blocks (8192/32).
__global__ void __launch_bounds__(256, 8)
lya_spec_kernel(const float* __restrict__ traj, float* __restrict__ out)
{
    const int bl = threadIdx.x & 31;   // b lane
    const int tl = threadIdx.x >> 5;   // t lane (0..7)
    const int b  = (blockIdx.x << 5) + bl;

    // q0 = row0 / |row0|, row0 = (0.9, 0.1, 0)
    const float Q00 = 0.99388373f;    // 0.9 / sqrt(0.82)
    const float Q01 = 0.110431530f;   // 0.1 / sqrt(0.82)
    const float F22 = 0.97333334f;    // 1 - DT*8/3

    float acc1 = 0.f, acc2 = 0.f;

    const float* p = traj + b + tl * STRIDE_T;  // advance by 8 steps each iter
    const long step = 8L * STRIDE_T;

#pragma unroll 4
    for (int t = tl; t < T_STEPS; t += 8) {
        const float x = p[0];
        const float y = p[BATCH];
        const float z = p[2 * BATCH];
        p += step;

        // J rows 1,2
        const float a = fmaf(-0.01f, z, 0.28f);   // 0.01*(28 - z)
        const float e = 0.01f * x;                // J21; J12 = -e
        const float d = 0.01f * y;                // J20

        // --- GS row 1 against q0 ---
        const float d10 = fmaf(Q00, a, Q01 * 0.99f);
        const float r10 = fmaf(-d10, Q00, a);
        const float r11 = fmaf(-d10, Q01, 0.99f);
        // r12 = -e
        float s1 = fmaf(r10, r10, fmaf(r11, r11, e * e));
        acc1 += flog2_approx(s1);

        // --- GS row 2 against q0 then q1 = r1/sqrt(s1) ---
        const float d20 = fmaf(Q00, d, Q01 * e);
        const float r20 = fmaf(-d20, Q00, d);
        const float r21 = fmaf(-d20, Q01, e);
        // r22 = F22 (q0 has zero z-component)

        // w = r1 . r2 ; subtract (w/s1) * r1
        const float w  = fmaf(r10, r20, fmaf(r11, r21, -e * F22));
        const float inv1 = frsqrt_approx(s1);
        const float wi = w * (inv1 * inv1);       // w / s1
        const float t0 = fmaf(-wi, r10, r20);
        const float t1 = fmaf(-wi, r11, r21);
        const float t2 = fmaf( wi, e,   F22);     // F22 - wi*(-e)
        const float s2 = fmaf(t0, t0, fmaf(t1, t1, t2 * t2));
        acc2 += flog2_approx(s2);
    }

    // 8-way reduction over t-lanes
    __shared__ float red[8][64];
    red[tl][bl]      = acc1;
    red[tl][32 + bl] = acc2;
    __syncthreads();

    // lambda = sum log(n) / (T*DT) = 0.5*ln2 * sum log2(s) / 20.48
    const float C = 0.016922539f;
    if (threadIdx.x < 64) {
        const int j = threadIdx.x;
        float s = red[0][j];
#pragma unroll
        for (int k = 1; k < 8; ++k) s += red[k][j];
        const int bb = (blockIdx.x << 5) + (j & 31);
        if (j < 32) {
            out[bb]         = -9.922547f;   // 50*ln(0.82), constant row 0
            out[BATCH + bb] = s * C;
        } else {
            out[2 * BATCH + bb] = s * C;
        }
    }
}

extern "C" void kernel_launch(void* const* d_in, const int* in_sizes, int n_in,
                              void* d_out, int out_size)
{
    const float* traj = (const float*)d_in[0];
    float* out = (float*)d_out;
    lya_spec_kernel<<<BATCH / 32, 256>>>(traj, out);
}

// round 4
// speedup vs baseline: 9.4696x; 2.0695x over previous
#include <cuda_runtime.h>
#include <cuda_bf16.h>

// Lyapunov spectrum, map-reduce form (see R2/R3 derivation):
// row-GS norms of J(x,y,z)@Q equal those of J alone (Q orthonormal), so
//   lambda_k(b) = sum_t log(n_k(x_t,y_t,z_t)) / (T*DT),
// a pure map-reduce over (t,b). Row 0 is the constant 50*ln(0.82).
//
// Stage 1: float4-vectorized over b, t split into 32 chunks x 8 t-lanes x 8
//          steps; block-reduce t-lanes -> per-(chunk,b4) partials in scratch.
// Stage 2: sum 32 chunk partials per output, write rows 1,2 and constant row 0.

#define T_STEPS 2048
#define BATCH   8192
#define B4      2048                 // BATCH/4
#define ROW4    2048                 // float4 per component row
#define STRIDE_T4 (3 * ROW4)         // 6144 float4 per time step
#define NCHUNK  32

__device__ float4 g_part1[NCHUNK][B4];
__device__ float4 g_part2[NCHUNK][B4];

__device__ __forceinline__ float frsqrt_approx(float x) {
    float r; asm("rsqrt.approx.f32 %0, %1;" : "=f"(r) : "f"(x)); return r;
}
__device__ __forceinline__ float flog2_approx(float x) {
    float r; asm("lg2.approx.f32 %0, %1;" : "=f"(r) : "f"(x)); return r;
}

// Per-sample GS norms (see R3). Adds log2(s1) to l1, log2(s2) to l2.
__device__ __forceinline__ void gs_sample(float x, float y, float z,
                                          float& l1, float& l2)
{
    const float Q00 = 0.99388373f;    // 0.9 / sqrt(0.82)
    const float Q01 = 0.110431530f;   // 0.1 / sqrt(0.82)
    const float F22 = 0.97333334f;    // 1 - DT*8/3

    const float a = fmaf(-0.01f, z, 0.28f);
    const float e = 0.01f * x;
    const float d = 0.01f * y;

    const float d10 = fmaf(Q00, a, Q01 * 0.99f);
    const float r10 = fmaf(-d10, Q00, a);
    const float r11 = fmaf(-d10, Q01, 0.99f);
    const float s1  = fmaf(r10, r10, fmaf(r11, r11, e * e));
    l1 += flog2_approx(s1);

    const float d20 = fmaf(Q00, d, Q01 * e);
    const float r20 = fmaf(-d20, Q00, d);
    const float r21 = fmaf(-d20, Q01, e);
    const float w   = fmaf(r10, r20, fmaf(r11, r21, -e * F22));
    const float inv1 = frsqrt_approx(s1);
    const float wi  = w * (inv1 * inv1);
    const float t0  = fmaf(-wi, r10, r20);
    const float t1  = fmaf(-wi, r11, r21);
    const float t2  = fmaf( wi, e,   F22);
    const float s2  = fmaf(t0, t0, fmaf(t1, t1, t2 * t2));
    l2 += flog2_approx(s2);
}

// grid: (64, 32)  block: 256 = 32 b4-lanes x 8 t-lanes
__global__ void __launch_bounds__(256, 6)
lya_main_kernel(const float4* __restrict__ traj4)
{
    const int bl = threadIdx.x & 31;
    const int tl = threadIdx.x >> 5;
    const int b4 = (blockIdx.x << 5) + bl;
    const int chunk = blockIdx.y;
    const int t0 = chunk * 64 + tl * 8;

    float4 acc1 = make_float4(0.f, 0.f, 0.f, 0.f);
    float4 acc2 = make_float4(0.f, 0.f, 0.f, 0.f);

    const float4* p = traj4 + (long)t0 * STRIDE_T4 + b4;

#pragma unroll 4
    for (int i = 0; i < 8; ++i) {
        const float4 xv = p[0];
        const float4 yv = p[ROW4];
        const float4 zv = p[2 * ROW4];
        p += STRIDE_T4;

        gs_sample(xv.x, yv.x, zv.x, acc1.x, acc2.x);
        gs_sample(xv.y, yv.y, zv.y, acc1.y, acc2.y);
        gs_sample(xv.z, yv.z, zv.z, acc1.z, acc2.z);
        gs_sample(xv.w, yv.w, zv.w, acc1.w, acc2.w);
    }

    // reduce over the 8 t-lanes
    __shared__ float4 red1[8][32];
    __shared__ float4 red2[8][32];
    red1[tl][bl] = acc1;
    red2[tl][bl] = acc2;
    __syncthreads();

    if (threadIdx.x < 64) {
        const int j = threadIdx.x & 31;
        if (threadIdx.x < 32) {
            float4 s = red1[0][j];
#pragma unroll
            for (int k = 1; k < 8; ++k) {
                s.x += red1[k][j].x; s.y += red1[k][j].y;
                s.z += red1[k][j].z; s.w += red1[k][j].w;
            }
            g_part1[chunk][(blockIdx.x << 5) + j] = s;
        } else {
            float4 s = red2[0][j];
#pragma unroll
            for (int k = 1; k < 8; ++k) {
                s.x += red2[k][j].x; s.y += red2[k][j].y;
                s.z += red2[k][j].z; s.w += red2[k][j].w;
            }
            g_part2[chunk][(blockIdx.x << 5) + j] = s;
        }
    }
}

// grid: 16 blocks x 256 threads; 4096 tasks (2048 for row1, 2048 for row2).
__global__ void __launch_bounds__(256)
lya_reduce_kernel(float4* __restrict__ out4)
{
    const int id = blockIdx.x * 256 + threadIdx.x;   // 0..4095
    const int b4 = id & (B4 - 1);
    const float C = 0.016922539f;     // 0.5*ln2 / 20.48

    const float4* part = (id < B4) ? &g_part1[0][b4] : &g_part2[0][b4];
    float4 s = make_float4(0.f, 0.f, 0.f, 0.f);
#pragma unroll 8
    for (int c = 0; c < NCHUNK; ++c) {
        const float4 v = part[(long)c * B4];
        s.x += v.x; s.y += v.y; s.z += v.z; s.w += v.w;
    }
    s.x *= C; s.y *= C; s.z *= C; s.w *= C;

    if (id < B4) {
        // constant row 0: 50*ln(0.82)
        out4[b4] = make_float4(-9.922547f, -9.922547f, -9.922547f, -9.922547f);
        out4[B4 + b4] = s;
    } else {
        out4[2 * B4 + b4] = s;
    }
}

extern "C" void kernel_launch(void* const* d_in, const int* in_sizes, int n_in,
                              void* d_out, int out_size)
{
    const float4* traj4 = (const float4*)d_in[0];
    float4* out4 = (float4*)d_out;
    dim3 grid(64, 32);
    lya_main_kernel<<<grid, 256>>>(traj4);
    lya_reduce_kernel<<<16, 256>>>(out4);
}

// round 5
// speedup vs baseline: 9.9884x; 1.0548x over previous
#include <cuda_runtime.h>
#include <cuda_bf16.h>

// Lyapunov spectrum, map-reduce form (see R2/R3 derivation):
// row-GS norms of J(x,y,z)@Q equal those of J alone (Q orthonormal), so
//   lambda_k(b) = sum_t log(n_k(x_t,y_t,z_t)) / (T*DT)
// Row 0 norm is constant sqrt(0.82). Pythagorean GS-norm form:
//   s1 = |row1|^2 - d10^2
//   s2 = |row2|^2 - d20^2 - (w/|r1|)^2,  w = r1 . row2
//
// Stage 1: float4 over b, t in 32 chunks x 8 t-lanes x 8 steps; block-reduce
//          t-lanes -> per-(chunk,b4) partials in device scratch.
// Stage 2: 128 blocks x 32 threads, one task per thread, 32 chunk loads.

#define T_STEPS 2048
#define BATCH   8192
#define B4      2048                 // BATCH/4
#define ROW4    2048                 // float4 per component row
#define STRIDE_T4 (3 * ROW4)         // 6144 float4 per time step
#define NCHUNK  32

__device__ float4 g_part1[NCHUNK][B4];
__device__ float4 g_part2[NCHUNK][B4];

__device__ __forceinline__ float frsqrt_approx(float x) {
    float r; asm("rsqrt.approx.f32 %0, %1;" : "=f"(r) : "f"(x)); return r;
}
__device__ __forceinline__ float flog2_approx(float x) {
    float r; asm("lg2.approx.f32 %0, %1;" : "=f"(r) : "f"(x)); return r;
}

// Per-sample GS norms. Adds log2(s1) to l1, log2(s2) to l2.
__device__ __forceinline__ void gs_sample(float x, float y, float z,
                                          float& l1, float& l2)
{
    const float Q00 = 0.99388373f;     // 0.9 / sqrt(0.82)
    const float Q01 = 0.110431530f;    // 0.1 / sqrt(0.82)
    const float F22 = 0.97333334f;     // 1 - DT*8/3
    const float C99SQ = 0.9801f;       // 0.99^2
    const float F22SQ = 0.94737780f;   // F22^2

    const float a = fmaf(-0.01f, z, 0.28f);   // J10
    const float e = 0.01f * x;                // J21 (= -J12)
    const float d = 0.01f * y;                // J20

    // row1 = (a, 0.99, -e)
    const float d10 = fmaf(Q00, a, Q01 * 0.99f);
    float s1 = fmaf(a, a, C99SQ);
    s1 = fmaf(e, e, s1);
    s1 = fmaf(-d10, d10, s1);
    l1 += flog2_approx(s1);

    // r1 = row1 - d10*q0 (z-component = -e)
    const float r10 = fmaf(-d10, Q00, a);
    const float r11 = fmaf(-d10, Q01, 0.99f);

    // row2 = (d, e, F22)
    const float d20 = fmaf(Q00, d, Q01 * e);
    const float w   = fmaf(r10, d, fmaf(r11, e, -e * F22));
    const float inv1 = frsqrt_approx(s1);
    const float wi  = w * inv1;
    float s2 = fmaf(d, d, F22SQ);
    s2 = fmaf(e, e, s2);
    s2 = fmaf(-d20, d20, s2);
    s2 = fmaf(-wi, wi, s2);
    l2 += flog2_approx(s2);
}

// grid: (64, 32)  block: 256 = 32 b4-lanes x 8 t-lanes
__global__ void __launch_bounds__(256, 6)
lya_main_kernel(const float4* __restrict__ traj4)
{
    const int bl = threadIdx.x & 31;
    const int tl = threadIdx.x >> 5;
    const int b4 = (blockIdx.x << 5) + bl;
    const int chunk = blockIdx.y;
    const int t0 = chunk * 64 + tl * 8;

    float4 acc1 = make_float4(0.f, 0.f, 0.f, 0.f);
    float4 acc2 = make_float4(0.f, 0.f, 0.f, 0.f);

    const float4* p = traj4 + (long)t0 * STRIDE_T4 + b4;

#pragma unroll
    for (int i = 0; i < 8; ++i) {
        const float4 xv = p[0];
        const float4 yv = p[ROW4];
        const float4 zv = p[2 * ROW4];
        p += STRIDE_T4;

        gs_sample(xv.x, yv.x, zv.x, acc1.x, acc2.x);
        gs_sample(xv.y, yv.y, zv.y, acc1.y, acc2.y);
        gs_sample(xv.z, yv.z, zv.z, acc1.z, acc2.z);
        gs_sample(xv.w, yv.w, zv.w, acc1.w, acc2.w);
    }

    // reduce over the 8 t-lanes
    __shared__ float4 red1[8][32];
    __shared__ float4 red2[8][32];
    red1[tl][bl] = acc1;
    red2[tl][bl] = acc2;
    __syncthreads();

    if (threadIdx.x < 64) {
        const int j = threadIdx.x & 31;
        if (threadIdx.x < 32) {
            float4 s = red1[0][j];
#pragma unroll
            for (int k = 1; k < 8; ++k) {
                s.x += red1[k][j].x; s.y += red1[k][j].y;
                s.z += red1[k][j].z; s.w += red1[k][j].w;
            }
            g_part1[chunk][(blockIdx.x << 5) + j] = s;
        } else {
            float4 s = red2[0][j];
#pragma unroll
            for (int k = 1; k < 8; ++k) {
                s.x += red2[k][j].x; s.y += red2[k][j].y;
                s.z += red2[k][j].z; s.w += red2[k][j].w;
            }
            g_part2[chunk][(blockIdx.x << 5) + j] = s;
        }
    }
}

// grid: 128 blocks x 32 threads = 4096 tasks (2048 row1 + 2048 row2).
// One task per thread; 32 chunk partials summed in 4 independent chains.
__global__ void __launch_bounds__(32)
lya_reduce_kernel(float4* __restrict__ out4)
{
    const int id = blockIdx.x * 32 + threadIdx.x;   // 0..4095
    const int b4 = id & (B4 - 1);
    const float C = 0.016922539f;     // 0.5*ln2 / 20.48

    const float4* part = (id < B4) ? &g_part1[0][b4] : &g_part2[0][b4];

    float4 s0 = make_float4(0.f, 0.f, 0.f, 0.f);
    float4 s1 = make_float4(0.f, 0.f, 0.f, 0.f);
    float4 s2 = make_float4(0.f, 0.f, 0.f, 0.f);
    float4 s3 = make_float4(0.f, 0.f, 0.f, 0.f);
#pragma unroll
    for (int c = 0; c < NCHUNK; c += 4) {
        const float4 v0 = part[(long)(c + 0) * B4];
        const float4 v1 = part[(long)(c + 1) * B4];
        const float4 v2 = part[(long)(c + 2) * B4];
        const float4 v3 = part[(long)(c + 3) * B4];
        s0.x += v0.x; s0.y += v0.y; s0.z += v0.z; s0.w += v0.w;
        s1.x += v1.x; s1.y += v1.y; s1.z += v1.z; s1.w += v1.w;
        s2.x += v2.x; s2.y += v2.y; s2.z += v2.z; s2.w += v2.w;
        s3.x += v3.x; s3.y += v3.y; s3.z += v3.z; s3.w += v3.w;
    }
    float4 s;
    s.x = (s0.x + s1.x) + (s2.x + s3.x);
    s.y = (s0.y + s1.y) + (s2.y + s3.y);
    s.z = (s0.z + s1.z) + (s2.z + s3.z);
    s.w = (s0.w + s1.w) + (s2.w + s3.w);
    s.x *= C; s.y *= C; s.z *= C; s.w *= C;

    if (id < B4) {
        // constant row 0: 50*ln(0.82)
        out4[b4] = make_float4(-9.922547f, -9.922547f, -9.922547f, -9.922547f);
        out4[B4 + b4] = s;
    } else {
        out4[2 * B4 + b4] = s;
    }
}

extern "C" void kernel_launch(void* const* d_in, const int* in_sizes, int n_in,
                              void* d_out, int out_size)
{
    const float4* traj4 = (const float4*)d_in[0];
    float4* out4 = (float4*)d_out;
    dim3 grid(64, 32);
    lya_main_kernel<<<grid, 256>>>(traj4);
    lya_reduce_kernel<<<128, 32>>>(out4);
}

// round 6
// speedup vs baseline: 10.0975x; 1.0109x over previous
#include <cuda_runtime.h>
#include <cuda_bf16.h>

// Lyapunov spectrum, map-reduce form (see R2/R3 derivation):
// row-GS norms of J(x,y,z)@Q equal those of J alone (Q orthonormal), so
//   lambda_k(b) = sum_t log(n_k(x_t,y_t,z_t)) / (T*DT)
// Row 0 norm is constant sqrt(0.82). Pythagorean GS-norm form:
//   s1 = |row1|^2 - d10^2
//   s2 = |row2|^2 - d20^2 - (w/|r1|)^2,  w = r1 . row2
//
// Stage 1: float4 over b, t in 32 chunks x 8 t-lanes x 8 steps; block-reduce
//          t-lanes -> per-(chunk,b4) partials in device scratch.
// Stage 2: 64 blocks x 256 threads = (32 b4 x 8 chunk-lanes), coalesced
//          L2-resident loads, 8-way smem reduce, write all 3 output rows.

#define T_STEPS 2048
#define BATCH   8192
#define B4      2048                 // BATCH/4
#define ROW4    2048                 // float4 per component row
#define STRIDE_T4 (3 * ROW4)         // 6144 float4 per time step
#define NCHUNK  32

__device__ float4 g_part1[NCHUNK][B4];
__device__ float4 g_part2[NCHUNK][B4];

__device__ __forceinline__ float frsqrt_approx(float x) {
    float r; asm("rsqrt.approx.f32 %0, %1;" : "=f"(r) : "f"(x)); return r;
}
__device__ __forceinline__ float flog2_approx(float x) {
    float r; asm("lg2.approx.f32 %0, %1;" : "=f"(r) : "f"(x)); return r;
}

// Per-sample GS norms. Adds log2(s1) to l1, log2(s2) to l2.
__device__ __forceinline__ void gs_sample(float x, float y, float z,
                                          float& l1, float& l2)
{
    const float Q00 = 0.99388373f;     // 0.9 / sqrt(0.82)
    const float Q01 = 0.110431530f;    // 0.1 / sqrt(0.82)
    const float F22 = 0.97333334f;     // 1 - DT*8/3
    const float C99SQ = 0.9801f;       // 0.99^2
    const float F22SQ = 0.94737780f;   // F22^2

    const float a = fmaf(-0.01f, z, 0.28f);   // J10
    const float e = 0.01f * x;                // J21 (= -J12)
    const float d = 0.01f * y;                // J20

    // row1 = (a, 0.99, -e)
    const float d10 = fmaf(Q00, a, Q01 * 0.99f);
    float s1 = fmaf(a, a, C99SQ);
    s1 = fmaf(e, e, s1);
    s1 = fmaf(-d10, d10, s1);
    l1 += flog2_approx(s1);

    // r1 = row1 - d10*q0 (z-component = -e)
    const float r10 = fmaf(-d10, Q00, a);
    const float r11 = fmaf(-d10, Q01, 0.99f);

    // row2 = (d, e, F22)
    const float d20 = fmaf(Q00, d, Q01 * e);
    const float w   = fmaf(r10, d, fmaf(r11, e, -e * F22));
    const float inv1 = frsqrt_approx(s1);
    const float wi  = w * inv1;
    float s2 = fmaf(d, d, F22SQ);
    s2 = fmaf(e, e, s2);
    s2 = fmaf(-d20, d20, s2);
    s2 = fmaf(-wi, wi, s2);
    l2 += flog2_approx(s2);
}

// grid: (64, 32)  block: 256 = 32 b4-lanes x 8 t-lanes
__global__ void __launch_bounds__(256, 4)
lya_main_kernel(const float4* __restrict__ traj4)
{
    const int bl = threadIdx.x & 31;
    const int tl = threadIdx.x >> 5;
    const int b4 = (blockIdx.x << 5) + bl;
    const int chunk = blockIdx.y;
    const int t0 = chunk * 64 + tl * 8;

    float4 acc1 = make_float4(0.f, 0.f, 0.f, 0.f);
    float4 acc2 = make_float4(0.f, 0.f, 0.f, 0.f);

    const float4* p = traj4 + (long)t0 * STRIDE_T4 + b4;

#pragma unroll
    for (int i = 0; i < 8; ++i) {
        const float4 xv = p[0];
        const float4 yv = p[ROW4];
        const float4 zv = p[2 * ROW4];
        p += STRIDE_T4;

        gs_sample(xv.x, yv.x, zv.x, acc1.x, acc2.x);
        gs_sample(xv.y, yv.y, zv.y, acc1.y, acc2.y);
        gs_sample(xv.z, yv.z, zv.z, acc1.z, acc2.z);
        gs_sample(xv.w, yv.w, zv.w, acc1.w, acc2.w);
    }

    // reduce over the 8 t-lanes
    __shared__ float4 red1[8][32];
    __shared__ float4 red2[8][32];
    red1[tl][bl] = acc1;
    red2[tl][bl] = acc2;
    __syncthreads();

    if (threadIdx.x < 64) {
        const int j = threadIdx.x & 31;
        if (threadIdx.x < 32) {
            float4 s = red1[0][j];
#pragma unroll
            for (int k = 1; k < 8; ++k) {
                s.x += red1[k][j].x; s.y += red1[k][j].y;
                s.z += red1[k][j].z; s.w += red1[k][j].w;
            }
            g_part1[chunk][(blockIdx.x << 5) + j] = s;
        } else {
            float4 s = red2[0][j];
#pragma unroll
            for (int k = 1; k < 8; ++k) {
                s.x += red2[k][j].x; s.y += red2[k][j].y;
                s.z += red2[k][j].z; s.w += red2[k][j].w;
            }
            g_part2[chunk][(blockIdx.x << 5) + j] = s;
        }
    }
}

// grid: 64 blocks x 256 threads = (32 b4-lanes x 8 chunk-lanes).
// Warp reads 32 consecutive b4 at one chunk -> coalesced, L2-resident.
__global__ void __launch_bounds__(256)
lya_reduce_kernel(float4* __restrict__ out4)
{
    const int bl = threadIdx.x & 31;   // b4 lane
    const int cl = threadIdx.x >> 5;   // chunk lane (0..7)
    const int b4 = (blockIdx.x << 5) + bl;

    // each thread sums chunks {cl, cl+8, cl+16, cl+24} for both rows
    float4 a1 = make_float4(0.f, 0.f, 0.f, 0.f);
    float4 a2 = make_float4(0.f, 0.f, 0.f, 0.f);
#pragma unroll
    for (int i = 0; i < 4; ++i) {
        const int c = cl + (i << 3);
        const float4 v1 = g_part1[c][b4];
        const float4 v2 = g_part2[c][b4];
        a1.x += v1.x; a1.y += v1.y; a1.z += v1.z; a1.w += v1.w;
        a2.x += v2.x; a2.y += v2.y; a2.z += v2.z; a2.w += v2.w;
    }

    __shared__ float4 red1[8][32];
    __shared__ float4 red2[8][32];
    red1[cl][bl] = a1;
    red2[cl][bl] = a2;
    __syncthreads();

    const float C = 0.016922539f;     // 0.5*ln2 / 20.48
    if (threadIdx.x < 64) {
        const int j = threadIdx.x & 31;
        const int bb = (blockIdx.x << 5) + j;
        if (threadIdx.x < 32) {
            float4 s = red1[0][j];
#pragma unroll
            for (int k = 1; k < 8; ++k) {
                s.x += red1[k][j].x; s.y += red1[k][j].y;
                s.z += red1[k][j].z; s.w += red1[k][j].w;
            }
            s.x *= C; s.y *= C; s.z *= C; s.w *= C;
            // constant row 0: 50*ln(0.82)
            out4[bb] = make_float4(-9.922547f, -9.922547f, -9.922547f, -9.922547f);
            out4[B4 + bb] = s;
        } else {
            float4 s = red2[0][j];
#pragma unroll
            for (int k = 1; k < 8; ++k) {
                s.x += red2[k][j].x; s.y += red2[k][j].y;
                s.z += red2[k][j].z; s.w += red2[k][j].w;
            }
            s.x *= C; s.y *= C; s.z *= C; s.w *= C;
            out4[2 * B4 + bb] = s;
        }
    }
}

extern "C" void kernel_launch(void* const* d_in, const int* in_sizes, int n_in,
                              void* d_out, int out_size)
{
    const float4* traj4 = (const float4*)d_in[0];
    float4* out4 = (float4*)d_out;
    dim3 grid(64, 32);
    lya_main_kernel<<<grid, 256>>>(traj4);
    lya_reduce_kernel<<<64, 256>>>(out4);
}